// round 8
// baseline (speedup 1.0000x reference)
#include <cuda_runtime.h>
#include <cuda_bf16.h>
#include <cstdint>

// ============================================================================
// BitLinear on GB300 (compute_103 base target — legacy mma.sync + dp4a):
//   out[m,n] = s[m] * wscale * sum_k q[m,k] * t[n,k]
// Dual-pipe GEMM, decoupled halves via mbarrier ring:
//   warps 0-7  : tensor pipe (mma.sync m16n8k32), N cols [0,144) {40,40,32,32}
//                + all cp.async production
//   warps 8-15 : fma pipe (dp4a), N cols [144,256) {32,32,24,24}
// No __syncthreads in the mainloop: per-stage full/empty mbarriers let each
// half run at its own pipe floor.
// ============================================================================

#define DIM_M 8192
#define DIM_N 16384
#define DIM_K 4096

#define BM 128
#define BN 256
#define BK 64
#define NK (DIM_K / BK)          // 64 chunks
#define STAGES 4

#define ROWB 80                  // 64B row + 16B pad: conflict-free, 16B-aligned
#define A_ST (BM * ROWB)         // 10240
#define B_ST (BN * ROWB)         // 20480
#define ST_BYTES (A_ST + B_ST)   // 30720
#define GEMM_SMEM (STAGES * ST_BYTES + 128)
#define GEMM_THREADS 512

// ---------------- device globals (static scratch; allocation-free) ----------
__device__ __align__(1024) int8_t g_Xq[(size_t)DIM_M * DIM_K];  // 32 MB
__device__ __align__(1024) int8_t g_Wq[(size_t)DIM_N * DIM_K];  // 64 MB
__device__ float g_Xs[DIM_M];
__device__ float g_partial[2048];
__device__ float g_wscale;

// ---------------- helpers ----------------------------------------------------
__device__ __forceinline__ uint32_t smem_u32(const void* p) {
    uint32_t a;
    asm("{ .reg .u64 t; cvta.to.shared.u64 t, %1; cvt.u32.u64 %0, t; }" : "=r"(a) : "l"(p));
    return a;
}

__device__ __forceinline__ void cp_async16(uint32_t dst, const void* src) {
    unsigned long long g = (unsigned long long)__cvta_generic_to_global(src);
    asm volatile("cp.async.cg.shared.global [%0], [%1], 16;" :: "r"(dst), "l"(g) : "memory");
}

__device__ __forceinline__ void ldsm_x4(uint32_t (&r)[4], uint32_t addr) {
    asm volatile("ldmatrix.sync.aligned.m8n8.x4.shared.b16 {%0,%1,%2,%3}, [%4];"
                 : "=r"(r[0]), "=r"(r[1]), "=r"(r[2]), "=r"(r[3]) : "r"(addr));
}
__device__ __forceinline__ void ldsm_x1(uint32_t& r, uint32_t addr) {
    asm volatile("ldmatrix.sync.aligned.m8n8.x1.shared.b16 {%0}, [%1];"
                 : "=r"(r) : "r"(addr));
}

__device__ __forceinline__ void mma_s8(int (&d)[4], const uint32_t (&a)[4],
                                       uint32_t b0, uint32_t b1) {
    asm volatile(
        "mma.sync.aligned.m16n8k32.row.col.s32.s8.s8.s32 "
        "{%0,%1,%2,%3}, {%4,%5,%6,%7}, {%8,%9}, {%0,%1,%2,%3};"
        : "+r"(d[0]), "+r"(d[1]), "+r"(d[2]), "+r"(d[3])
        : "r"(a[0]), "r"(a[1]), "r"(a[2]), "r"(a[3]), "r"(b0), "r"(b1));
}

__device__ __forceinline__ void lds_v4(uint32_t (&r)[4], uint32_t addr) {
    asm volatile("ld.shared.v4.b32 {%0,%1,%2,%3}, [%4];"
                 : "=r"(r[0]), "=r"(r[1]), "=r"(r[2]), "=r"(r[3]) : "r"(addr));
}

__device__ __forceinline__ int dp4a_(uint32_t a, uint32_t b, int c) {
    int d;
    asm("dp4a.s32.s32 %0, %1, %2, %3;" : "=r"(d) : "r"(a), "r"(b), "r"(c));
    return d;
}

#define MBARRIER_INIT(addr, count) \
    asm volatile("mbarrier.init.shared.b64 [%0], %1;" :: "r"((uint32_t)(addr)), "r"((uint32_t)(count)) : "memory")

#define MBARRIER_ARRIVE(addr) \
    asm volatile("mbarrier.arrive.shared.b64 _, [%0];" :: "r"((uint32_t)(addr)) : "memory")

#define CPASYNC_MBAR_ARRIVE(addr) \
    asm volatile("cp.async.mbarrier.arrive.noinc.shared.b64 [%0];" :: "r"((uint32_t)(addr)) : "memory")

#define MBARRIER_WAIT_PARITY(mbar_smem_addr, phase_parity) do {                             \
    uint32_t _mbar = (uint32_t)(mbar_smem_addr);                                            \
    uint32_t _parity = (uint32_t)(phase_parity);                                            \
    uint32_t _done;                                                                         \
    asm volatile(                                                                           \
        "{\n\t.reg .pred p;\n\t"                                                            \
        "mbarrier.try_wait.parity.shared.b64 p, [%1], %2;\n\t"                              \
        "selp.b32 %0, 1, 0, p;\n\t}"                                                        \
        : "=r"(_done) : "r"(_mbar), "r"(_parity) : "memory");                               \
    if (!_done) {                                                                           \
        asm volatile(                                                                       \
            "{\n\t.reg .pred P1;\n\t"                                                       \
            "WAIT_LOOP_%=:\n\t"                                                             \
            "mbarrier.try_wait.parity.shared.b64 P1, [%0], %1;\n\t"                         \
            "@P1 bra.uni WAIT_DONE_%=;\n\t"                                                 \
            "bra.uni WAIT_LOOP_%=;\n\t"                                                     \
            "WAIT_DONE_%=:\n\t}"                                                            \
            :: "r"(_mbar), "r"(_parity) : "memory");                                        \
    }                                                                                       \
} while (0)

// ============================================================================
// Kernel 1: partial |W| sums (deterministic fixed order)
// ============================================================================
__global__ void __launch_bounds__(256) wabs_partial(const float* __restrict__ w) {
    const int tid = threadIdx.x;
    const float4* w4 = reinterpret_cast<const float4*>(w);
    const size_t total4 = (size_t)DIM_N * DIM_K / 4;
    float s = 0.0f;
    for (size_t i = (size_t)blockIdx.x * blockDim.x + tid; i < total4;
         i += (size_t)gridDim.x * blockDim.x) {
        float4 v = w4[i];
        s += fabsf(v.x) + fabsf(v.y) + fabsf(v.z) + fabsf(v.w);
    }
    #pragma unroll
    for (int o = 16; o; o >>= 1) s += __shfl_xor_sync(0xFFFFFFFFu, s, o);
    __shared__ float sm[8];
    if ((tid & 31) == 0) sm[tid >> 5] = s;
    __syncthreads();
    if (tid == 0) {
        float t = 0.0f;
        #pragma unroll
        for (int i = 0; i < 8; i++) t += sm[i];
        g_partial[blockIdx.x] = t;
    }
}

__global__ void __launch_bounds__(256) wscale_finalize() {
    const int tid = threadIdx.x;
    float s = 0.0f;
    for (int i = tid; i < 2048; i += 256) s += g_partial[i];
    #pragma unroll
    for (int o = 16; o; o >>= 1) s += __shfl_xor_sync(0xFFFFFFFFu, s, o);
    __shared__ float sm[8];
    if ((tid & 31) == 0) sm[tid >> 5] = s;
    __syncthreads();
    if (tid == 0) {
        float t = 0.0f;
        #pragma unroll
        for (int i = 0; i < 8; i++) t += sm[i];
        float mean = t * (1.0f / 67108864.0f);   // exact /2^26
        g_wscale = fmaxf(mean, 1e-5f);
    }
}

// ============================================================================
// Kernel 2 (fused): blocks [0, 65536) quantize W; blocks [65536, 73728) quant X
// ============================================================================
__device__ __forceinline__ int q_int4(float x, float s) {
    float d = __fdividef(x, s);
    float r = rintf(d);
    if (fabsf(d - r) > 0.4995f)
        r = rintf(__fdiv_rn(x, s));
    r = fminf(fmaxf(r, -8.0f), 7.0f);
    return (int)r;
}

#define WQ_BLOCKS 65536

__global__ void __launch_bounds__(256) quant_wx_kernel(const float* __restrict__ w,
                                                       const float* __restrict__ x) {
    const int tid = threadIdx.x;
    if (blockIdx.x < WQ_BLOCKS) {
        const size_t i4 = (size_t)blockIdx.x * 256 + tid;
        const float ws = g_wscale;
        const float half = 0.5f * ws;
        const float band = half * 1.000001f;
        float4 v = reinterpret_cast<const float4*>(w)[i4];
        int t[4];
        float e[4] = {v.x, v.y, v.z, v.w};
        #pragma unroll
        for (int j = 0; j < 4; j++) {
            float aw = fabsf(e[j]);
            int tv = (aw > half) ? 1 : 0;
            if (tv && aw < band)
                tv = (int)fminf(rintf(__fdiv_rn(aw, ws)), 1.0f);
            t[j] = (e[j] < 0.0f) ? -tv : tv;
        }
        uint32_t pk = (uint32_t)(t[0] & 0xFF) | ((uint32_t)(t[1] & 0xFF) << 8) |
                      ((uint32_t)(t[2] & 0xFF) << 16) | ((uint32_t)t[3] << 24);
        reinterpret_cast<uint32_t*>(g_Wq)[i4] = pk;
    } else {
        const int token = blockIdx.x - WQ_BLOCKS;
        const float4* row = reinterpret_cast<const float4*>(x + (size_t)token * DIM_K);
        float4 v[4];
        float am = 0.0f;
        #pragma unroll
        for (int i = 0; i < 4; i++) {
            v[i] = row[tid + 256 * i];
            am = fmaxf(am, fmaxf(fmaxf(fabsf(v[i].x), fabsf(v[i].y)),
                                 fmaxf(fabsf(v[i].z), fabsf(v[i].w))));
        }
        #pragma unroll
        for (int o = 16; o; o >>= 1) am = fmaxf(am, __shfl_xor_sync(0xFFFFFFFFu, am, o));
        __shared__ float sm[8];
        __shared__ float s_bcast;
        if ((tid & 31) == 0) sm[tid >> 5] = am;
        __syncthreads();
        if (tid == 0) {
            float t = sm[0];
            #pragma unroll
            for (int i = 1; i < 8; i++) t = fmaxf(t, sm[i]);
            float s = __fdiv_rn(fmaxf(t, 1e-5f), 7.0f);
            s_bcast = s;
            g_Xs[token] = s;
        }
        __syncthreads();
        const float s = s_bcast;
        uint32_t* orow = reinterpret_cast<uint32_t*>(g_Xq + (size_t)token * DIM_K);
        #pragma unroll
        for (int i = 0; i < 4; i++) {
            int a = q_int4(v[i].x, s), b = q_int4(v[i].y, s);
            int c = q_int4(v[i].z, s), d = q_int4(v[i].w, s);
            uint32_t pk = (uint32_t)(a & 0xFF) | ((uint32_t)(b & 0xFF) << 8) |
                          ((uint32_t)(c & 0xFF) << 16) | ((uint32_t)d << 24);
            orow[tid + 256 * i] = pk;
        }
    }
}

// ============================================================================
// Kernel 3: decoupled dual-pipe GEMM
// ============================================================================
__device__ __forceinline__ void load_tile(uint32_t dstbase, int m0, int n0,
                                          int chunk, int tid256) {
    const int k0 = chunk * BK;
    #pragma unroll
    for (int i = 0; i < 2; i++) {        // A: 128 rows x 64B = 512 segs
        int seg = tid256 + i * 256;
        int r = seg >> 2, c = seg & 3;
        cp_async16(dstbase + r * ROWB + c * 16,
                   g_Xq + (size_t)(m0 + r) * DIM_K + k0 + c * 16);
    }
    #pragma unroll
    for (int i = 0; i < 4; i++) {        // B: 256 rows -> 1024 segs
        int seg = tid256 + i * 256;
        int r = seg >> 2, c = seg & 3;
        cp_async16(dstbase + A_ST + r * ROWB + c * 16,
                   g_Wq + (size_t)(n0 + r) * DIM_K + k0 + c * 16);
    }
}

// One mainloop instantiation per (role, fragment-count).
template <bool IS_T, int NF>
__device__ __forceinline__ void gemm_mainloop(
    uint32_t sb, uint32_t ctrl, int m0, int n0, int tid,
    uint32_t op_a_off, uint32_t op_b_off, uint32_t op_b1_off,
    int (&acc)[4][5][4])
{
    for (int kc = 0; kc < NK; kc++) {
        const int s = kc & 3, r = kc >> 2;

        if (IS_T) {
            // ---- producer: fill stage for chunk kc+3 ----
            const int f = kc + (STAGES - 1);
            if (f < NK) {
                const int sf = f & 3, rf = f >> 2;
                if (rf > 0) MBARRIER_WAIT_PARITY(ctrl + sf * 16 + 8, (rf - 1) & 1);
                load_tile(sb + (uint32_t)sf * ST_BYTES, m0, n0, f, tid);
                CPASYNC_MBAR_ARRIVE(ctrl + sf * 16);
            }
        }

        // ---- consumer: wait data ----
        MBARRIER_WAIT_PARITY(ctrl + s * 16, r & 1);
        const uint32_t sbase = sb + (uint32_t)s * ST_BYTES;

        if (IS_T) {
            const uint32_t a_base = sbase + op_a_off;
            const uint32_t b_base = sbase + op_b_off;
            const uint32_t b1_base = sbase + op_b1_off;
            #pragma unroll
            for (int ksi = 0; ksi < 2; ksi++) {
                uint32_t af[4][4];
                #pragma unroll
                for (int mf = 0; mf < 4; mf++)
                    ldsm_x4(af[mf], a_base + mf * (16 * ROWB) + ksi * 32);
                uint32_t b0[4], b1[4];
                ldsm_x4(b0, b_base + ksi * 32);
                ldsm_x4(b1, b_base + ksi * 32 + 16);
                uint32_t e0 = 0, e1 = 0;
                if (NF == 5) {
                    ldsm_x1(e0, b1_base + ksi * 32);
                    ldsm_x1(e1, b1_base + ksi * 32 + 16);
                }
                #pragma unroll
                for (int mf = 0; mf < 4; mf++) {
                    #pragma unroll
                    for (int nf = 0; nf < 4; nf++)
                        mma_s8(acc[mf][nf], af[mf], b0[nf], b1[nf]);
                    if (NF == 5)
                        mma_s8(acc[mf][4], af[mf], e0, e1);
                }
            }
        } else {
            const uint32_t a_base = sbase + op_a_off;
            const uint32_t b_base = sbase + op_b_off;
            #pragma unroll
            for (int kq = 0; kq < 4; kq++) {            // 16 k-bytes per iter
                uint32_t bf[NF][2][4];
                #pragma unroll
                for (int nf = 0; nf < NF; nf++)
                    #pragma unroll
                    for (int cc = 0; cc < 2; cc++)
                        lds_v4(bf[nf][cc],
                               b_base + (uint32_t)((nf * 8 + cc) * ROWB + kq * 16));
                #pragma unroll
                for (int mf = 0; mf < 4; mf++) {
                    uint32_t af[2][4];
                    lds_v4(af[0], a_base + (uint32_t)((mf * 16 + 0) * ROWB + kq * 16));
                    lds_v4(af[1], a_base + (uint32_t)((mf * 16 + 8) * ROWB + kq * 16));
                    #pragma unroll
                    for (int nf = 0; nf < NF; nf++)
                        #pragma unroll
                        for (int w = 0; w < 4; w++) {
                            acc[mf][nf][0] = dp4a_(af[0][w], bf[nf][0][w], acc[mf][nf][0]);
                            acc[mf][nf][1] = dp4a_(af[0][w], bf[nf][1][w], acc[mf][nf][1]);
                            acc[mf][nf][2] = dp4a_(af[1][w], bf[nf][0][w], acc[mf][nf][2]);
                            acc[mf][nf][3] = dp4a_(af[1][w], bf[nf][1][w], acc[mf][nf][3]);
                        }
                }
            }
        }

        // ---- signal stage consumed ----
        MBARRIER_ARRIVE(ctrl + s * 16 + 8);
    }
}

__global__ void __launch_bounds__(GEMM_THREADS, 1) bitlinear_gemm(float* __restrict__ out) {
    extern __shared__ char smem_raw[];
    const uint32_t sb = smem_u32(smem_raw);
    const uint32_t ctrl = sb + STAGES * ST_BYTES;  // 8 mbarriers: full/empty x4

    const int tid = threadIdx.x;
    const int lane = tid & 31;
    const int wid = tid >> 5;
    const bool is_t = (wid < 8);
    const int w8 = wid & 7;
    const int wm = w8 & 1;             // M halves (64 rows each)
    const int wn = w8 >> 1;            // 4 N-groups per side

    const int bid = blockIdx.x;
    const int g = bid >> 9;            // groups of 8 M-tiles sweep 64 N-tiles
    const int r = bid & 511;
    const int m0 = (g * 8 + (r & 7)) * BM;
    const int n0 = (r >> 3) * BN;

    // column split: tensor {40,40,32,32} @ {0,40,80,112}; dp {32,32,24,24} @ {144,176,208,232}
    const int nft = (wn < 2) ? 5 : 4;
    const int base_t = wn * 40 - ((wn == 3) ? 8 : 0);
    const int nfd = (wn < 2) ? 4 : 3;
    const int base_d = 144 + wn * 32 - ((wn == 3) ? 8 : 0);

    uint32_t op_a, op_b, op_b1;
    if (is_t) {
        op_a  = (uint32_t)((wm * 64 + (lane & 15)) * ROWB + (lane >> 4) * 16);
        op_b  = (uint32_t)(A_ST + (base_t + lane) * ROWB);
        op_b1 = (uint32_t)(A_ST + (base_t + 32 + (lane & 7)) * ROWB);
    } else {
        op_a  = (uint32_t)((wm * 64 + (lane >> 2)) * ROWB);
        op_b  = (uint32_t)(A_ST + (base_d + 2 * (lane & 3)) * ROWB);
        op_b1 = 0;
    }

    int acc[4][5][4];
    #pragma unroll
    for (int i = 0; i < 4; i++)
        #pragma unroll
        for (int j = 0; j < 5; j++)
            #pragma unroll
            for (int k = 0; k < 4; k++) acc[i][j][k] = 0;

    // init mbarriers: full count = 256 (async arrivals from tensor threads),
    // empty count = 512 (every thread arrives after consuming a stage)
    if (tid == 0) {
        #pragma unroll
        for (int s = 0; s < STAGES; s++) {
            MBARRIER_INIT(ctrl + s * 16, 256);
            MBARRIER_INIT(ctrl + s * 16 + 8, 512);
        }
    }
    __syncthreads();

    // prologue: tensor warps fill stages 0..2
    if (is_t) {
        #pragma unroll
        for (int f = 0; f < STAGES - 1; f++) {
            load_tile(sb + (uint32_t)f * ST_BYTES, m0, n0, f, tid);
            CPASYNC_MBAR_ARRIVE(ctrl + f * 16);
        }
    }

    if (is_t) {
        if (wn < 2) gemm_mainloop<true, 5>(sb, ctrl, m0, n0, tid, op_a, op_b, op_b1, acc);
        else        gemm_mainloop<true, 4>(sb, ctrl, m0, n0, tid, op_a, op_b, op_b1, acc);
    } else {
        if (wn < 2) gemm_mainloop<false, 4>(sb, ctrl, m0, n0, tid, op_a, op_b, op_b1, acc);
        else        gemm_mainloop<false, 3>(sb, ctrl, m0, n0, tid, op_a, op_b, op_b1, acc);
    }

    // ---------------- epilogue: scale by s[m]*wscale, write fp32 -------------
    const float ws = g_wscale;
    const int nfc = is_t ? nft : nfd;
    const int m_base = m0 + wm * 64;
    const int n_base = n0 + (is_t ? base_t : base_d);
    const int lr = lane >> 2, lc = lane & 3;

    #pragma unroll
    for (int mf = 0; mf < 4; mf++) {
        const int r0 = m_base + mf * 16 + lr;
        const float s0 = g_Xs[r0] * ws;
        const float s1 = g_Xs[r0 + 8] * ws;
        float* p0 = out + (size_t)r0 * DIM_N + n_base + 2 * lc;
        float* p1 = p0 + (size_t)8 * DIM_N;
        for (int nf = 0; nf < nfc; nf++) {
            float2 v0, v1;
            v0.x = __int2float_rn(acc[mf][nf][0]) * s0;
            v0.y = __int2float_rn(acc[mf][nf][1]) * s0;
            v1.x = __int2float_rn(acc[mf][nf][2]) * s1;
            v1.y = __int2float_rn(acc[mf][nf][3]) * s1;
            *reinterpret_cast<float2*>(p0 + nf * 8) = v0;
            *reinterpret_cast<float2*>(p1 + nf * 8) = v1;
        }
    }
}

// ============================================================================
extern "C" void kernel_launch(void* const* d_in, const int* in_sizes, int n_in,
                              void* d_out, int out_size) {
    const float* x = (const float*)d_in[0];   // (4, 2048, 4096) fp32
    const float* w = (const float*)d_in[1];   // (16384, 4096) fp32
    float* out = (float*)d_out;               // (4, 2048, 16384) fp32
    (void)in_sizes; (void)n_in; (void)out_size;

    cudaFuncSetAttribute(bitlinear_gemm, cudaFuncAttributeMaxDynamicSharedMemorySize, GEMM_SMEM);

    wabs_partial<<<2048, 256>>>(w);
    wscale_finalize<<<1, 256>>>();
    quant_wx_kernel<<<WQ_BLOCKS + DIM_M, 256>>>(w, x);

    const int grid = (DIM_M / BM) * (DIM_N / BN);  // 64 * 64 = 4096
    bitlinear_gemm<<<grid, GEMM_THREADS, GEMM_SMEM>>>(out);
}